// round 1
// baseline (speedup 1.0000x reference)
#include <cuda_runtime.h>
#include <math.h>

#define BATCH 4096
#define MSET  8192
#define DIM   1024
#define HID   4096
#define OUTD  1000
#define CAP   2048

// ---------------- scratch (static device globals: no allocation) ----------------
__device__ float g_XN[(size_t)BATCH * DIM];       // normalized encoder
__device__ float g_YN[(size_t)MSET  * DIM];       // normalized memory
__device__ float g_S [(size_t)BATCH * MSET];      // similarities / dense weights (fallback)
__device__ float g_MV[(size_t)BATCH * DIM];       // memory vector
__device__ float g_FI[(size_t)BATCH * 2 * DIM];   // [enc | mv]
__device__ float g_H [(size_t)BATCH * HID];       // hidden
__device__ int   g_cnt[BATCH];                    // support size per row (-1 => dense fallback)
__device__ int   g_idx[(size_t)BATCH * CAP];
__device__ float g_w  [(size_t)BATCH * CAP];

// ---------------- reductions ----------------
__device__ __forceinline__ float warp_sum(float v) {
#pragma unroll
    for (int o = 16; o > 0; o >>= 1) v += __shfl_down_sync(0xffffffffu, v, o);
    return v;
}
__device__ __forceinline__ float warp_max(float v) {
#pragma unroll
    for (int o = 16; o > 0; o >>= 1) v = fmaxf(v, __shfl_down_sync(0xffffffffu, v, o));
    return v;
}
// 256-thread block reductions; buf must hold >= 8 floats
__device__ __forceinline__ float block_sum(float v, float* buf) {
    int tid = threadIdx.x, w = tid >> 5, l = tid & 31;
    v = warp_sum(v);
    __syncthreads();
    if (l == 0) buf[w] = v;
    __syncthreads();
    if (tid == 0) {
        float s = 0.f;
#pragma unroll
        for (int i = 0; i < 8; i++) s += buf[i];
        buf[0] = s;
    }
    __syncthreads();
    return buf[0];
}
__device__ __forceinline__ float block_max(float v, float* buf) {
    int tid = threadIdx.x, w = tid >> 5, l = tid & 31;
    v = warp_max(v);
    __syncthreads();
    if (l == 0) buf[w] = v;
    __syncthreads();
    if (tid == 0) {
        float s = buf[0];
#pragma unroll
        for (int i = 1; i < 8; i++) s = fmaxf(s, buf[i]);
        buf[0] = s;
    }
    __syncthreads();
    return buf[0];
}

// ---------------- 1) row normalization ----------------
// one block per row, 256 threads, DIM=1024 -> 1 float4 per thread
template <int WHICH>  // 0: encoder -> g_XN ; 1: memory -> g_YN
__global__ __launch_bounds__(256) void normalize_rows(const float* __restrict__ src) {
    __shared__ float buf[8];
    float* dst = (WHICH == 0) ? g_XN : g_YN;
    size_t row = blockIdx.x;
    int tid = threadIdx.x;
    const float4* s4 = reinterpret_cast<const float4*>(src) + row * (DIM / 4);
    float4* d4 = reinterpret_cast<float4*>(dst) + row * (DIM / 4);
    float4 v = s4[tid];
    float ss = v.x * v.x + v.y * v.y + v.z * v.z + v.w * v.w;
    ss = block_sum(ss, buf);
    float inv = rsqrtf(ss + 1e-6f);
    v.x *= inv; v.y *= inv; v.z *= inv; v.w *= inv;
    d4[tid] = v;
}

// ---------------- 2) NT GEMM: C[M,N] = A[M,K] * B[N,K]^T (+bias)(+relu) ----------------
// BM=BN=128, BK=16, 256 threads, 8x8 micro-tile per thread.
// MODE 0: A=g_XN, B=g_YN, C=g_S
// MODE 1: A=g_FI, B=Bext(W1), C=g_H
// MODE 2: A=g_H,  B=Bext(W2), C=Cext(out)
template <int MODE, bool BIAS, bool RELU>
__global__ __launch_bounds__(256) void gemm_nt(const float* __restrict__ Bext,
                                               const float* __restrict__ bias,
                                               float* __restrict__ Cext,
                                               int M, int N, int K) {
    const int BM = 128, BN = 128, BK = 16;
    __shared__ float As[BK * BM];
    __shared__ float Bs[BK * BN];

    const float* A;
    const float* B;
    float* C;
    if (MODE == 0)      { A = g_XN; B = g_YN; C = g_S; }
    else if (MODE == 1) { A = g_FI; B = Bext; C = g_H; }
    else                { A = g_H;  B = Bext; C = Cext; }

    int tid = threadIdx.x;
    int bm = blockIdx.y * BM;
    int bn = blockIdx.x * BN;
    int tx = tid & 15;         // N direction
    int ty = tid >> 4;         // M direction

    float acc[8][8];
#pragma unroll
    for (int i = 0; i < 8; i++)
#pragma unroll
        for (int j = 0; j < 8; j++) acc[i][j] = 0.f;

    for (int k0 = 0; k0 < K; k0 += BK) {
        // load A tile (128 rows x 16 k), 512 float4 loads, transpose into As[k][m]
#pragma unroll
        for (int e = tid; e < 512; e += 256) {
            int r = e >> 2, kq = e & 3;
            float4 v = *reinterpret_cast<const float4*>(A + (size_t)(bm + r) * K + k0 + kq * 4);
            As[(kq * 4 + 0) * BM + r] = v.x;
            As[(kq * 4 + 1) * BM + r] = v.y;
            As[(kq * 4 + 2) * BM + r] = v.z;
            As[(kq * 4 + 3) * BM + r] = v.w;
        }
#pragma unroll
        for (int e = tid; e < 512; e += 256) {
            int r = e >> 2, kq = e & 3;
            float4 v = make_float4(0.f, 0.f, 0.f, 0.f);
            if (bn + r < N)
                v = *reinterpret_cast<const float4*>(B + (size_t)(bn + r) * K + k0 + kq * 4);
            Bs[(kq * 4 + 0) * BN + r] = v.x;
            Bs[(kq * 4 + 1) * BN + r] = v.y;
            Bs[(kq * 4 + 2) * BN + r] = v.z;
            Bs[(kq * 4 + 3) * BN + r] = v.w;
        }
        __syncthreads();

#pragma unroll
        for (int k = 0; k < BK; k++) {
            float a[8], b[8];
            *reinterpret_cast<float4*>(a)     = *reinterpret_cast<const float4*>(&As[k * BM + ty * 8]);
            *reinterpret_cast<float4*>(a + 4) = *reinterpret_cast<const float4*>(&As[k * BM + ty * 8 + 4]);
            *reinterpret_cast<float4*>(b)     = *reinterpret_cast<const float4*>(&Bs[k * BN + tx * 8]);
            *reinterpret_cast<float4*>(b + 4) = *reinterpret_cast<const float4*>(&Bs[k * BN + tx * 8 + 4]);
#pragma unroll
            for (int i = 0; i < 8; i++)
#pragma unroll
                for (int j = 0; j < 8; j++)
                    acc[i][j] = fmaf(a[i], b[j], acc[i][j]);
        }
        __syncthreads();
    }

#pragma unroll
    for (int i = 0; i < 8; i++) {
        int mrow = bm + ty * 8 + i;
        float* crow = C + (size_t)mrow * N;
#pragma unroll
        for (int j = 0; j < 8; j++) {
            int n = bn + tx * 8 + j;
            if (n < N) {
                float v = acc[i][j];
                if (BIAS) v += bias[n];
                if (RELU) v = fmaxf(v, 0.f);
                crow[n] = v;
            }
        }
    }
}

// ---------------- 3) sparsemax per row (Newton on tau), emit sparse lists ----------------
__global__ __launch_bounds__(256) void sparsemax_kernel() {
    __shared__ float z[MSET];    // 32 KB row cache
    __shared__ float bufA[8];
    __shared__ float bufB[8];
    __shared__ int sh_pos;

    size_t row = blockIdx.x;
    int tid = threadIdx.x;
    float* srow = g_S + row * (size_t)MSET;

    // load row + max
    const float4* s4 = reinterpret_cast<const float4*>(srow);
    float4* z4 = reinterpret_cast<float4*>(z);
    float mx = -1e30f;
    for (int i = tid; i < MSET / 4; i += 256) {
        float4 v = s4[i];
        z4[i] = v;
        mx = fmaxf(mx, fmaxf(fmaxf(v.x, v.y), fmaxf(v.z, v.w)));
    }
    mx = block_max(mx, bufA);

    // Newton: tau <- (sum_{z>tau} z - 1) / count, starting from tau = max - 1 (f(tau) >= 0)
    float tau = mx - 1.0f;
    for (int it = 0; it < 64; ++it) {
        float s = 0.f, c = 0.f;
        for (int i = tid; i < MSET; i += 256) {
            float v = z[i];
            if (v > tau) { s += v; c += 1.f; }
        }
        s = block_sum(s, bufA);
        c = block_sum(c, bufB);
        float tn = (s - 1.0f) / c;
        if (!(tn > tau)) break;   // monotone increase; exact fixed point reached
        tau = tn;
    }

    // compact nonzeros (order irrelevant: MV is a weighted sum)
    if (tid == 0) sh_pos = 0;
    __syncthreads();
    int* il = g_idx + row * (size_t)CAP;
    float* wl = g_w + row * (size_t)CAP;
    for (int i = tid; i < MSET; i += 256) {
        float v = z[i] - tau;
        if (v > 0.f) {
            int p = atomicAdd(&sh_pos, 1);
            if (p < CAP) { il[p] = i; wl[p] = v; }
        }
    }
    __syncthreads();
    int total = sh_pos;
    if (total > CAP) {
        // dense fallback: materialize weights into S for this row
        for (int i = tid; i < MSET; i += 256) srow[i] = fmaxf(z[i] - tau, 0.f);
        if (tid == 0) g_cnt[row] = -1;
    } else {
        if (tid == 0) g_cnt[row] = total;
    }
}

// ---------------- 4) memory_vector = CW @ memory_set (sparse gather) ----------------
__global__ __launch_bounds__(256) void sparse_mv(const float* __restrict__ mem) {
    size_t row = blockIdx.x;
    int tid = threadIdx.x;
    int cnt = g_cnt[row];
    const float4* Y4 = reinterpret_cast<const float4*>(mem);
    float4 acc = make_float4(0.f, 0.f, 0.f, 0.f);

    if (cnt >= 0) {
        const int* il = g_idx + row * (size_t)CAP;
        const float* wl = g_w + row * (size_t)CAP;
        int t = 0;
        for (; t + 4 <= cnt; t += 4) {
#pragma unroll
            for (int u = 0; u < 4; u++) {
                int j = il[t + u];
                float w = wl[t + u];
                float4 y = Y4[(size_t)j * (DIM / 4) + tid];
                acc.x = fmaf(w, y.x, acc.x);
                acc.y = fmaf(w, y.y, acc.y);
                acc.z = fmaf(w, y.z, acc.z);
                acc.w = fmaf(w, y.w, acc.w);
            }
        }
        for (; t < cnt; t++) {
            int j = il[t];
            float w = wl[t];
            float4 y = Y4[(size_t)j * (DIM / 4) + tid];
            acc.x = fmaf(w, y.x, acc.x);
            acc.y = fmaf(w, y.y, acc.y);
            acc.z = fmaf(w, y.z, acc.z);
            acc.w = fmaf(w, y.w, acc.w);
        }
    } else {
        const float* srow = g_S + row * (size_t)MSET;
        for (int j = 0; j < MSET; j++) {
            float w = srow[j];
            if (w > 0.f) {
                float4 y = Y4[(size_t)j * (DIM / 4) + tid];
                acc.x = fmaf(w, y.x, acc.x);
                acc.y = fmaf(w, y.y, acc.y);
                acc.z = fmaf(w, y.z, acc.z);
                acc.w = fmaf(w, y.w, acc.w);
            }
        }
    }
    reinterpret_cast<float4*>(g_MV)[row * (DIM / 4) + tid] = acc;
}

// ---------------- 5) concat [enc | mv] -> FI ----------------
__global__ __launch_bounds__(256) void concat_kernel(const float* __restrict__ enc) {
    size_t i = (size_t)blockIdx.x * 256 + threadIdx.x;   // float4 index over [BATCH, 2*DIM/4=512]
    size_t row = i >> 9;
    int c4 = (int)(i & 511);
    float4 v;
    if (c4 < 256) v = reinterpret_cast<const float4*>(enc)[row * 256 + c4];
    else          v = reinterpret_cast<const float4*>(g_MV)[row * 256 + (c4 - 256)];
    reinterpret_cast<float4*>(g_FI)[i] = v;
}

// ---------------- launch ----------------
extern "C" void kernel_launch(void* const* d_in, const int* in_sizes, int n_in,
                              void* d_out, int out_size) {
    const float* enc = (const float*)d_in[0];   // [4096,1024]
    const float* mem = (const float*)d_in[1];   // [8192,1024]
    // d_in[2] loss_weights: unused by forward
    const float* W1 = (const float*)d_in[3];    // [4096,2048]
    const float* b1 = (const float*)d_in[4];    // [4096]
    const float* W2 = (const float*)d_in[5];    // [1000,4096]
    const float* b2 = (const float*)d_in[6];    // [1000]
    float* out = (float*)d_out;                 // [4096,1000]

    normalize_rows<0><<<BATCH, 256>>>(enc);
    normalize_rows<1><<<MSET, 256>>>(mem);

    {   // S = XN @ YN^T
        dim3 grid(MSET / 128, BATCH / 128);
        gemm_nt<0, false, false><<<grid, 256>>>(nullptr, nullptr, nullptr, BATCH, MSET, DIM);
    }

    sparsemax_kernel<<<BATCH, 256>>>();
    sparse_mv<<<BATCH, 256>>>(mem);
    concat_kernel<<<(BATCH * 512) / 256, 256>>>(enc);

    {   // H = relu(FI @ W1^T + b1)
        dim3 grid(HID / 128, BATCH / 128);
        gemm_nt<1, true, true><<<grid, 256>>>(W1, b1, nullptr, BATCH, HID, 2 * DIM);
    }
    {   // out = H @ W2^T + b2
        dim3 grid((OUTD + 127) / 128, BATCH / 128);
        gemm_nt<2, true, false><<<grid, 256>>>(W2, b2, out, BATCH, OUTD, HID);
    }
}

// round 2
// speedup vs baseline: 3.5831x; 3.5831x over previous
#include <cuda_runtime.h>
#include <math.h>

#define BATCH 4096
#define MSET  8192
#define DIM   1024
#define HID   4096
#define OUTD  1000
#define CAP   2048

// ---------------- scratch (static device globals: no allocation) ----------------
__device__ float g_XN[(size_t)BATCH * DIM];       // normalized encoder (tf32-rounded)
__device__ float g_YN[(size_t)MSET  * DIM];       // normalized memory (tf32-rounded)
__device__ float g_S [(size_t)BATCH * MSET];      // similarities / dense weights (fallback)
__device__ float g_MV[(size_t)BATCH * DIM];       // memory vector
__device__ float g_FI[(size_t)BATCH * 2 * DIM];   // [enc | mv] (tf32-rounded)
__device__ float g_H [(size_t)BATCH * HID];       // hidden (tf32-rounded)
__device__ float g_W1r[(size_t)HID * 2 * DIM];    // W1 tf32-rounded
__device__ float g_W2r[(size_t)OUTD * HID];       // W2 tf32-rounded
__device__ int   g_cnt[BATCH];
__device__ int   g_idx[(size_t)BATCH * CAP];
__device__ float g_w  [(size_t)BATCH * CAP];

// ---------------- small helpers ----------------
__device__ __forceinline__ float tf32_rna(float x) {
    float r;
    asm("cvt.rna.tf32.f32 %0, %1;\n" : "=f"(r) : "f"(x));
    return r;
}
__device__ __forceinline__ void cp_async16(float* sdst, const float* gsrc, int nbytes) {
    unsigned s = (unsigned)__cvta_generic_to_shared(sdst);
    asm volatile("cp.async.cg.shared.global [%0], [%1], 16, %2;\n"
                 :: "r"(s), "l"(gsrc), "r"(nbytes) : "memory");
}
#define CP_COMMIT() asm volatile("cp.async.commit_group;\n" ::: "memory")
#define CP_WAIT1()  asm volatile("cp.async.wait_group 1;\n" ::: "memory")

__device__ __forceinline__ void mma_tf32(float c[4], const unsigned a[4], const unsigned b[2]) {
    asm volatile(
        "mma.sync.aligned.m16n8k8.row.col.f32.tf32.tf32.f32 "
        "{%0,%1,%2,%3}, {%4,%5,%6,%7}, {%8,%9}, {%0,%1,%2,%3};\n"
        : "+f"(c[0]), "+f"(c[1]), "+f"(c[2]), "+f"(c[3])
        : "r"(a[0]), "r"(a[1]), "r"(a[2]), "r"(a[3]), "r"(b[0]), "r"(b[1]));
}

__device__ __forceinline__ float warp_sum(float v) {
#pragma unroll
    for (int o = 16; o > 0; o >>= 1) v += __shfl_down_sync(0xffffffffu, v, o);
    return v;
}
__device__ __forceinline__ float warp_max(float v) {
#pragma unroll
    for (int o = 16; o > 0; o >>= 1) v = fmaxf(v, __shfl_down_sync(0xffffffffu, v, o));
    return v;
}
__device__ __forceinline__ float block_sum(float v, float* buf) {
    int tid = threadIdx.x, w = tid >> 5, l = tid & 31;
    v = warp_sum(v);
    __syncthreads();
    if (l == 0) buf[w] = v;
    __syncthreads();
    if (tid == 0) {
        float s = 0.f;
#pragma unroll
        for (int i = 0; i < 8; i++) s += buf[i];
        buf[0] = s;
    }
    __syncthreads();
    return buf[0];
}
__device__ __forceinline__ float block_max(float v, float* buf) {
    int tid = threadIdx.x, w = tid >> 5, l = tid & 31;
    v = warp_max(v);
    __syncthreads();
    if (l == 0) buf[w] = v;
    __syncthreads();
    if (tid == 0) {
        float s = buf[0];
#pragma unroll
        for (int i = 1; i < 8; i++) s = fmaxf(s, buf[i]);
        buf[0] = s;
    }
    __syncthreads();
    return buf[0];
}

// ---------------- 1) row normalization (+ tf32 round) ----------------
template <int WHICH>
__global__ __launch_bounds__(256) void normalize_rows(const float* __restrict__ src) {
    __shared__ float buf[8];
    float* dst = (WHICH == 0) ? g_XN : g_YN;
    size_t row = blockIdx.x;
    int tid = threadIdx.x;
    const float4* s4 = reinterpret_cast<const float4*>(src) + row * (DIM / 4);
    float4* d4 = reinterpret_cast<float4*>(dst) + row * (DIM / 4);
    float4 v = s4[tid];
    float ss = v.x * v.x + v.y * v.y + v.z * v.z + v.w * v.w;
    ss = block_sum(ss, buf);
    float inv = rsqrtf(ss + 1e-6f);
    v.x = tf32_rna(v.x * inv); v.y = tf32_rna(v.y * inv);
    v.z = tf32_rna(v.z * inv); v.w = tf32_rna(v.w * inv);
    d4[tid] = v;
}

// ---------------- 1b) round W1/W2 to tf32 ----------------
template <int WHICH>  // 0 -> g_W1r, 1 -> g_W2r
__global__ __launch_bounds__(256) void round_weights(const float* __restrict__ src, int n4) {
    float* dst = (WHICH == 0) ? g_W1r : g_W2r;
    int i = blockIdx.x * 256 + threadIdx.x;
    if (i < n4) {
        float4 v = reinterpret_cast<const float4*>(src)[i];
        v.x = tf32_rna(v.x); v.y = tf32_rna(v.y);
        v.z = tf32_rna(v.z); v.w = tf32_rna(v.w);
        reinterpret_cast<float4*>(dst)[i] = v;
    }
}

// ---------------- 2) tensor-core NT GEMM: C[M,N] = A[M,K] * B[N,K]^T ----------------
// 128x128 tile, BK=32, 4 warps (64x64 each), mma.sync m16n8k8 tf32, cp.async 2-stage.
// MODE 0: A=g_XN, B=g_YN, C=g_S
// MODE 1: A=g_FI, B=g_W1r, C=g_H      (+bias +relu +round)
// MODE 2: A=g_H,  B=g_W2r, C=Cext     (+bias, N-guard)
#define SMEM_STRIDE 36
#define GEMM_SMEM_BYTES (2 * 2 * 128 * SMEM_STRIDE * 4)

template <int MODE, bool BIAS, bool RELU, bool ROUND, bool NGUARD>
__global__ __launch_bounds__(128, 2) void gemm_tc(const float* __restrict__ bias,
                                                  float* __restrict__ Cext,
                                                  int M, int N, int K) {
    extern __shared__ float smem[];
    float* As = smem;                       // [2][128][36]
    float* Bs = smem + 2 * 128 * SMEM_STRIDE;

    const float* A;
    const float* B;
    float* C;
    if (MODE == 0)      { A = g_XN; B = g_YN;  C = g_S; }
    else if (MODE == 1) { A = g_FI; B = g_W1r; C = g_H; }
    else                { A = g_H;  B = g_W2r; C = Cext; }

    int tid = threadIdx.x;
    int lane = tid & 31;
    int warp = tid >> 5;
    int wm = warp & 1, wn = warp >> 1;       // 2x2 warp grid
    int g = lane >> 2, tig = lane & 3;

    int bm = blockIdx.y * 128;
    int bn = blockIdx.x * 128;

    float acc[4][8][4];
#pragma unroll
    for (int i = 0; i < 4; i++)
#pragma unroll
        for (int j = 0; j < 8; j++)
#pragma unroll
            for (int q = 0; q < 4; q++) acc[i][j][q] = 0.f;

    int lrow = tid >> 3;       // 0..15
    int lcol = tid & 7;        // 0..7 (float4 index along K)

    int kTiles = K / 32;

    auto load_stage = [&](int t, int st) {
        const float* Ag = A + (size_t)bm * K + t * 32;
        const float* Bg = B + (size_t)bn * K + t * 32;
        float* as = As + st * 128 * SMEM_STRIDE;
        float* bs = Bs + st * 128 * SMEM_STRIDE;
#pragma unroll
        for (int rep = 0; rep < 8; rep++) {
            int r = rep * 16 + lrow;
            cp_async16(&as[r * SMEM_STRIDE + lcol * 4], Ag + (size_t)r * K + lcol * 4, 16);
            int rr = r;
            int nbytes = 16;
            if (NGUARD && bn + r >= N) { rr = 0; nbytes = 0; }
            cp_async16(&bs[r * SMEM_STRIDE + lcol * 4], Bg + (size_t)rr * K + lcol * 4, nbytes);
        }
    };

    load_stage(0, 0);
    CP_COMMIT();

    for (int t = 0; t < kTiles; t++) {
        if (t + 1 < kTiles) load_stage(t + 1, (t + 1) & 1);
        CP_COMMIT();
        CP_WAIT1();
        __syncthreads();

        const float* as = As + (t & 1) * 128 * SMEM_STRIDE + (wm * 64) * SMEM_STRIDE;
        const float* bs = Bs + (t & 1) * 128 * SMEM_STRIDE + (wn * 64) * SMEM_STRIDE;

#pragma unroll
        for (int ks = 0; ks < 4; ks++) {
            int kk = ks * 8;
            unsigned a[4][4], b[8][2];
#pragma unroll
            for (int i = 0; i < 4; i++) {
                const float* ap = as + (i * 16 + g) * SMEM_STRIDE + kk + tig;
                a[i][0] = __float_as_uint(ap[0]);
                a[i][1] = __float_as_uint(ap[8 * SMEM_STRIDE]);
                a[i][2] = __float_as_uint(ap[4]);
                a[i][3] = __float_as_uint(ap[8 * SMEM_STRIDE + 4]);
            }
#pragma unroll
            for (int j = 0; j < 8; j++) {
                const float* bp = bs + (j * 8 + g) * SMEM_STRIDE + kk + tig;
                b[j][0] = __float_as_uint(bp[0]);
                b[j][1] = __float_as_uint(bp[4]);
            }
#pragma unroll
            for (int i = 0; i < 4; i++)
#pragma unroll
                for (int j = 0; j < 8; j++)
                    mma_tf32(acc[i][j], a[i], b[j]);
        }
        __syncthreads();
    }

    // epilogue: c0,c1 -> (row, col..col+1), c2,c3 -> (row+8, col..col+1)
#pragma unroll
    for (int i = 0; i < 4; i++) {
        int r0 = bm + wm * 64 + i * 16 + g;
#pragma unroll
        for (int j = 0; j < 8; j++) {
            int col = bn + wn * 64 + j * 8 + tig * 2;
            if (NGUARD && col >= N) continue;
            float bv0 = 0.f, bv1 = 0.f;
            if (BIAS) { bv0 = __ldg(bias + col); bv1 = __ldg(bias + col + 1); }
            float v0 = acc[i][j][0] + bv0;
            float v1 = acc[i][j][1] + bv1;
            float v2 = acc[i][j][2] + bv0;
            float v3 = acc[i][j][3] + bv1;
            if (RELU) { v0 = fmaxf(v0, 0.f); v1 = fmaxf(v1, 0.f); v2 = fmaxf(v2, 0.f); v3 = fmaxf(v3, 0.f); }
            if (ROUND) { v0 = tf32_rna(v0); v1 = tf32_rna(v1); v2 = tf32_rna(v2); v3 = tf32_rna(v3); }
            *reinterpret_cast<float2*>(C + (size_t)r0 * N + col)       = make_float2(v0, v1);
            *reinterpret_cast<float2*>(C + (size_t)(r0 + 8) * N + col) = make_float2(v2, v3);
        }
    }
}

// ---------------- 3) sparsemax per row (Newton on tau), emit sparse lists ----------------
__global__ __launch_bounds__(256) void sparsemax_kernel() {
    __shared__ float z[MSET];
    __shared__ float bufA[8];
    __shared__ float bufB[8];
    __shared__ int sh_pos;

    size_t row = blockIdx.x;
    int tid = threadIdx.x;
    float* srow = g_S + row * (size_t)MSET;

    const float4* s4 = reinterpret_cast<const float4*>(srow);
    float4* z4 = reinterpret_cast<float4*>(z);
    float mx = -1e30f;
    for (int i = tid; i < MSET / 4; i += 256) {
        float4 v = s4[i];
        z4[i] = v;
        mx = fmaxf(mx, fmaxf(fmaxf(v.x, v.y), fmaxf(v.z, v.w)));
    }
    mx = block_max(mx, bufA);

    float tau = mx - 1.0f;
    for (int it = 0; it < 64; ++it) {
        float s = 0.f, c = 0.f;
        for (int i = tid; i < MSET; i += 256) {
            float v = z[i];
            if (v > tau) { s += v; c += 1.f; }
        }
        s = block_sum(s, bufA);
        c = block_sum(c, bufB);
        float tn = (s - 1.0f) / c;
        if (!(tn > tau)) break;
        tau = tn;
    }

    if (tid == 0) sh_pos = 0;
    __syncthreads();
    int* il = g_idx + row * (size_t)CAP;
    float* wl = g_w + row * (size_t)CAP;
    for (int i = tid; i < MSET; i += 256) {
        float v = z[i] - tau;
        if (v > 0.f) {
            int p = atomicAdd(&sh_pos, 1);
            if (p < CAP) { il[p] = i; wl[p] = v; }
        }
    }
    __syncthreads();
    int total = sh_pos;
    if (total > CAP) {
        for (int i = tid; i < MSET; i += 256) srow[i] = fmaxf(z[i] - tau, 0.f);
        if (tid == 0) g_cnt[row] = -1;
    } else {
        if (tid == 0) g_cnt[row] = total;
    }
}

// ---------------- 4) memory_vector = CW @ memory_set (sparse gather) ----------------
__global__ __launch_bounds__(256) void sparse_mv(const float* __restrict__ mem) {
    size_t row = blockIdx.x;
    int tid = threadIdx.x;
    int cnt = g_cnt[row];
    const float4* Y4 = reinterpret_cast<const float4*>(mem);
    float4 acc = make_float4(0.f, 0.f, 0.f, 0.f);

    if (cnt >= 0) {
        const int* il = g_idx + row * (size_t)CAP;
        const float* wl = g_w + row * (size_t)CAP;
        int t = 0;
        for (; t + 4 <= cnt; t += 4) {
#pragma unroll
            for (int u = 0; u < 4; u++) {
                int j = il[t + u];
                float w = wl[t + u];
                float4 y = Y4[(size_t)j * (DIM / 4) + tid];
                acc.x = fmaf(w, y.x, acc.x);
                acc.y = fmaf(w, y.y, acc.y);
                acc.z = fmaf(w, y.z, acc.z);
                acc.w = fmaf(w, y.w, acc.w);
            }
        }
        for (; t < cnt; t++) {
            int j = il[t];
            float w = wl[t];
            float4 y = Y4[(size_t)j * (DIM / 4) + tid];
            acc.x = fmaf(w, y.x, acc.x);
            acc.y = fmaf(w, y.y, acc.y);
            acc.z = fmaf(w, y.z, acc.z);
            acc.w = fmaf(w, y.w, acc.w);
        }
    } else {
        const float* srow = g_S + row * (size_t)MSET;
        for (int j = 0; j < MSET; j++) {
            float w = srow[j];
            if (w > 0.f) {
                float4 y = Y4[(size_t)j * (DIM / 4) + tid];
                acc.x = fmaf(w, y.x, acc.x);
                acc.y = fmaf(w, y.y, acc.y);
                acc.z = fmaf(w, y.z, acc.z);
                acc.w = fmaf(w, y.w, acc.w);
            }
        }
    }
    reinterpret_cast<float4*>(g_MV)[row * (DIM / 4) + tid] = acc;
}

// ---------------- 5) concat [enc | mv] -> FI (tf32-rounded) ----------------
__global__ __launch_bounds__(256) void concat_kernel(const float* __restrict__ enc) {
    size_t i = (size_t)blockIdx.x * 256 + threadIdx.x;
    size_t row = i >> 9;
    int c4 = (int)(i & 511);
    float4 v;
    if (c4 < 256) v = reinterpret_cast<const float4*>(enc)[row * 256 + c4];
    else          v = reinterpret_cast<const float4*>(g_MV)[row * 256 + (c4 - 256)];
    v.x = tf32_rna(v.x); v.y = tf32_rna(v.y);
    v.z = tf32_rna(v.z); v.w = tf32_rna(v.w);
    reinterpret_cast<float4*>(g_FI)[i] = v;
}

// ---------------- launch ----------------
extern "C" void kernel_launch(void* const* d_in, const int* in_sizes, int n_in,
                              void* d_out, int out_size) {
    const float* enc = (const float*)d_in[0];   // [4096,1024]
    const float* mem = (const float*)d_in[1];   // [8192,1024]
    const float* W1 = (const float*)d_in[3];    // [4096,2048]
    const float* b1 = (const float*)d_in[4];    // [4096]
    const float* W2 = (const float*)d_in[5];    // [1000,4096]
    const float* b2 = (const float*)d_in[6];    // [1000]
    float* out = (float*)d_out;                 // [4096,1000]

    cudaFuncSetAttribute(gemm_tc<0, false, false, false, false>,
                         cudaFuncAttributeMaxDynamicSharedMemorySize, GEMM_SMEM_BYTES);
    cudaFuncSetAttribute(gemm_tc<1, true, true, true, false>,
                         cudaFuncAttributeMaxDynamicSharedMemorySize, GEMM_SMEM_BYTES);
    cudaFuncSetAttribute(gemm_tc<2, true, false, false, true>,
                         cudaFuncAttributeMaxDynamicSharedMemorySize, GEMM_SMEM_BYTES);

    normalize_rows<0><<<BATCH, 256>>>(enc);
    normalize_rows<1><<<MSET, 256>>>(mem);
    round_weights<0><<<(HID * 2 * DIM / 4 + 255) / 256, 256>>>(W1, HID * 2 * DIM / 4);
    round_weights<1><<<(OUTD * HID / 4 + 255) / 256, 256>>>(W2, OUTD * HID / 4);

    {   // S = XN @ YN^T
        dim3 grid(MSET / 128, BATCH / 128);
        gemm_tc<0, false, false, false, false><<<grid, 128, GEMM_SMEM_BYTES>>>(
            nullptr, nullptr, BATCH, MSET, DIM);
    }

    sparsemax_kernel<<<BATCH, 256>>>();
    sparse_mv<<<BATCH, 256>>>(mem);
    concat_kernel<<<(BATCH * 512) / 256, 256>>>(enc);

    {   // H = relu(FI @ W1r^T + b1), rounded to tf32
        dim3 grid(HID / 128, BATCH / 128);
        gemm_tc<1, true, true, true, false><<<grid, 128, GEMM_SMEM_BYTES>>>(
            b1, nullptr, BATCH, HID, 2 * DIM);
    }
    {   // out = H @ W2r^T + b2
        dim3 grid((OUTD + 127) / 128, BATCH / 128);
        gemm_tc<2, true, false, false, true><<<grid, 128, GEMM_SMEM_BYTES>>>(
            b2, out, BATCH, OUTD, HID);
    }
}

// round 4
// speedup vs baseline: 6.0768x; 1.6960x over previous
#include <cuda_runtime.h>
#include <cuda_fp16.h>
#include <math.h>
#include <stdint.h>

#define BATCH 4096
#define MSET  8192
#define DIM   1024
#define HID   4096
#define OUTD  1000
#define OUTP  1024
#define CAP   2048

// ---------------- scratch (static device globals: no allocation) ----------------
__device__ __half g_XNh[(size_t)BATCH * DIM];
__device__ __half g_YNh[(size_t)MSET  * DIM];
__device__ float  g_S  [(size_t)BATCH * MSET];
__device__ float  g_MV [(size_t)BATCH * DIM];
__device__ __half g_FIh[(size_t)BATCH * 2 * DIM];
__device__ __half g_Hh [(size_t)BATCH * HID];
__device__ __half g_W1h[(size_t)HID * 2 * DIM];
__device__ __half g_W2h[(size_t)OUTP * HID];     // rows 1000..1023 zero-padded
__device__ int    g_cnt[BATCH];
__device__ int    g_idx[(size_t)BATCH * CAP];
__device__ float  g_w  [(size_t)BATCH * CAP];

// ---------------- helpers ----------------
__device__ __forceinline__ void cpa16(void* sdst, const void* gsrc) {
    unsigned s = (unsigned)__cvta_generic_to_shared(sdst);
    asm volatile("cp.async.cg.shared.global [%0], [%1], 16;\n" :: "r"(s), "l"(gsrc) : "memory");
}
#define CPA_COMMIT() asm volatile("cp.async.commit_group;\n" ::: "memory")
#define CPA_WAIT1()  asm volatile("cp.async.wait_group 1;\n" ::: "memory")

__device__ __forceinline__ void mma_fp16(float c[4], const unsigned a[4], const unsigned b[2]) {
    asm volatile(
        "mma.sync.aligned.m16n8k16.row.col.f32.f16.f16.f32 "
        "{%0,%1,%2,%3}, {%4,%5,%6,%7}, {%8,%9}, {%0,%1,%2,%3};\n"
        : "+f"(c[0]), "+f"(c[1]), "+f"(c[2]), "+f"(c[3])
        : "r"(a[0]), "r"(a[1]), "r"(a[2]), "r"(a[3]), "r"(b[0]), "r"(b[1]));
}

__device__ __forceinline__ float warp_sum(float v) {
#pragma unroll
    for (int o = 16; o > 0; o >>= 1) v += __shfl_down_sync(0xffffffffu, v, o);
    return v;
}
__device__ __forceinline__ float warp_max(float v) {
#pragma unroll
    for (int o = 16; o > 0; o >>= 1) v = fmaxf(v, __shfl_down_sync(0xffffffffu, v, o));
    return v;
}
__device__ __forceinline__ float block_sum(float v, float* buf) {
    int tid = threadIdx.x, w = tid >> 5, l = tid & 31;
    v = warp_sum(v);
    __syncthreads();
    if (l == 0) buf[w] = v;
    __syncthreads();
    if (tid == 0) {
        float s = 0.f;
#pragma unroll
        for (int i = 0; i < 8; i++) s += buf[i];
        buf[0] = s;
    }
    __syncthreads();
    return buf[0];
}
__device__ __forceinline__ float block_max(float v, float* buf) {
    int tid = threadIdx.x, w = tid >> 5, l = tid & 31;
    v = warp_max(v);
    __syncthreads();
    if (l == 0) buf[w] = v;
    __syncthreads();
    if (tid == 0) {
        float s = buf[0];
#pragma unroll
        for (int i = 1; i < 8; i++) s = fmaxf(s, buf[i]);
        buf[0] = s;
    }
    __syncthreads();
    return buf[0];
}

// ---------------- 1) row normalization -> half ----------------
template <int WHICH>
__global__ __launch_bounds__(256) void normalize_rows(const float* __restrict__ src) {
    __shared__ float buf[8];
    __half* dst = (WHICH == 0) ? g_XNh : g_YNh;
    size_t row = blockIdx.x;
    int tid = threadIdx.x;
    const float4* s4 = reinterpret_cast<const float4*>(src) + row * (DIM / 4);
    float4 v = s4[tid];
    float ss = v.x * v.x + v.y * v.y + v.z * v.z + v.w * v.w;
    ss = block_sum(ss, buf);
    float inv = rsqrtf(ss + 1e-6f);
    __half2 h0 = __floats2half2_rn(v.x * inv, v.y * inv);
    __half2 h1 = __floats2half2_rn(v.z * inv, v.w * inv);
    uint2 u = make_uint2(*reinterpret_cast<unsigned*>(&h0), *reinterpret_cast<unsigned*>(&h1));
    reinterpret_cast<uint2*>(dst)[row * (DIM / 4) + tid] = u;
}

// ---------------- 1b) convert W1/W2 -> half (W2 zero-padded) ----------------
template <int WHICH>
__global__ __launch_bounds__(256) void conv_weights(const float* __restrict__ src, int n4src, int n4tot) {
    __half* dst = (WHICH == 0) ? g_W1h : g_W2h;
    int i = blockIdx.x * 256 + threadIdx.x;
    if (i >= n4tot) return;
    uint2 u = make_uint2(0u, 0u);
    if (i < n4src) {
        float4 v = reinterpret_cast<const float4*>(src)[i];
        __half2 h0 = __floats2half2_rn(v.x, v.y);
        __half2 h1 = __floats2half2_rn(v.z, v.w);
        u = make_uint2(*reinterpret_cast<unsigned*>(&h0), *reinterpret_cast<unsigned*>(&h1));
    }
    reinterpret_cast<uint2*>(dst)[i] = u;
}

// ---------------- 2) fp16 tensor-core NT GEMM: C[M,N] = A[M,K] * B[N,K]^T ----------------
// 128x128 CTA tile, BK=64 halves, 4 warps (64x64 each), mma m16n8k16, cp.async 2-stage.
// MODE 0: A=g_XNh, B=g_YNh, C=g_S (float)
// MODE 1: A=g_FIh, B=g_W1h, C=g_Hh (half, +bias +relu)
// MODE 2: A=g_Hh,  B=g_W2h, C=Cext (float, +bias, N-guard)
#define HSTRIDE 72                      // halves per smem row (64 + 8 pad)
#define STAGE_H (128 * HSTRIDE)         // 9216 halves per matrix per stage
#define GEMM_SMEM_BYTES (2 * 2 * STAGE_H * 2)   // 73728

template <int MODE, bool BIAS, bool RELU, bool NGUARD>
__global__ __launch_bounds__(128, 2) void gemm_fp16(const float* __restrict__ bias,
                                                    float* __restrict__ Cext,
                                                    int N, int K) {
    extern __shared__ __half sh[];

    const __half* A;
    const __half* B;
    if (MODE == 0)      { A = g_XNh; B = g_YNh; }
    else if (MODE == 1) { A = g_FIh; B = g_W1h; }
    else                { A = g_Hh;  B = g_W2h; }

    int tid = threadIdx.x;
    int lane = tid & 31;
    int warp = tid >> 5;
    int wm = warp & 1, wn = warp >> 1;
    int g = lane >> 2, tig = lane & 3;

    int bm = blockIdx.y * 128;
    int bn = blockIdx.x * 128;

    float acc[4][8][4];
#pragma unroll
    for (int i = 0; i < 4; i++)
#pragma unroll
        for (int j = 0; j < 8; j++)
#pragma unroll
            for (int q = 0; q < 4; q++) acc[i][j][q] = 0.f;

    int kT = K >> 6;

    const __half* Abase = A + (size_t)bm * K;
    const __half* Bbase = B + (size_t)bn * K;

    auto load_stage = [&](int t) {
        int st = t & 1;
        __half* sA = sh + st * (2 * STAGE_H);
        __half* sB = sA + STAGE_H;
        const __half* Ag = Abase + t * 64;
        const __half* Bg = Bbase + t * 64;
#pragma unroll
        for (int it = 0; it < 8; it++) {
            int idx = it * 128 + tid;
            int row = idx >> 3, ch = idx & 7;
            cpa16(sA + row * HSTRIDE + ch * 8, Ag + (size_t)row * K + ch * 8);
            cpa16(sB + row * HSTRIDE + ch * 8, Bg + (size_t)row * K + ch * 8);
        }
    };

    load_stage(0);
    CPA_COMMIT();

    for (int t = 0; t < kT; t++) {
        if (t + 1 < kT) load_stage(t + 1);
        CPA_COMMIT();
        CPA_WAIT1();
        __syncthreads();

        const __half* as = sh + (t & 1) * (2 * STAGE_H) + (wm * 64) * HSTRIDE;
        const __half* bs = sh + (t & 1) * (2 * STAGE_H) + STAGE_H + (wn * 64) * HSTRIDE;

#pragma unroll
        for (int kk = 0; kk < 4; kk++) {
            int kb = kk * 16;
            unsigned a[4][4], b[8][2];
#pragma unroll
            for (int i = 0; i < 4; i++) {
                const __half* ap = as + (i * 16 + g) * HSTRIDE + kb + 2 * tig;
                a[i][0] = *reinterpret_cast<const unsigned*>(ap);
                a[i][1] = *reinterpret_cast<const unsigned*>(ap + 8 * HSTRIDE);
                a[i][2] = *reinterpret_cast<const unsigned*>(ap + 8);
                a[i][3] = *reinterpret_cast<const unsigned*>(ap + 8 * HSTRIDE + 8);
            }
#pragma unroll
            for (int j = 0; j < 8; j++) {
                const __half* bp = bs + (j * 8 + g) * HSTRIDE + kb + 2 * tig;
                b[j][0] = *reinterpret_cast<const unsigned*>(bp);
                b[j][1] = *reinterpret_cast<const unsigned*>(bp + 8);
            }
#pragma unroll
            for (int i = 0; i < 4; i++)
#pragma unroll
                for (int j = 0; j < 8; j++)
                    mma_fp16(acc[i][j], a[i], b[j]);
        }
        __syncthreads();
    }

    // epilogue: c0,c1 -> (row, col, col+1); c2,c3 -> (row+8, col, col+1)
#pragma unroll
    for (int i = 0; i < 4; i++) {
        int r0 = bm + wm * 64 + i * 16 + g;
#pragma unroll
        for (int j = 0; j < 8; j++) {
            int col = bn + wn * 64 + j * 8 + tig * 2;
            if (NGUARD && col >= N) continue;
            float bv0 = 0.f, bv1 = 0.f;
            if (BIAS) { bv0 = __ldg(bias + col); bv1 = __ldg(bias + col + 1); }
            float v0 = acc[i][j][0] + bv0;
            float v1 = acc[i][j][1] + bv1;
            float v2 = acc[i][j][2] + bv0;
            float v3 = acc[i][j][3] + bv1;
            if (RELU) {
                v0 = fmaxf(v0, 0.f); v1 = fmaxf(v1, 0.f);
                v2 = fmaxf(v2, 0.f); v3 = fmaxf(v3, 0.f);
            }
            if (MODE == 1) {
                __half2 h0 = __floats2half2_rn(v0, v1);
                __half2 h1 = __floats2half2_rn(v2, v3);
                *reinterpret_cast<unsigned*>(g_Hh + (size_t)r0 * N + col) =
                    *reinterpret_cast<unsigned*>(&h0);
                *reinterpret_cast<unsigned*>(g_Hh + (size_t)(r0 + 8) * N + col) =
                    *reinterpret_cast<unsigned*>(&h1);
            } else {
                float* C = (MODE == 0) ? g_S : Cext;
                *reinterpret_cast<float2*>(C + (size_t)r0 * N + col)       = make_float2(v0, v1);
                *reinterpret_cast<float2*>(C + (size_t)(r0 + 8) * N + col) = make_float2(v2, v3);
            }
        }
    }
}

// ---------------- 3) sparsemax per row (Newton on tau), emit sparse lists ----------------
__global__ __launch_bounds__(256) void sparsemax_kernel() {
    __shared__ float z[MSET];
    __shared__ float bufA[8];
    __shared__ float bufB[8];
    __shared__ int sh_pos;

    size_t row = blockIdx.x;
    int tid = threadIdx.x;
    float* srow = g_S + row * (size_t)MSET;

    const float4* s4 = reinterpret_cast<const float4*>(srow);
    float4* z4 = reinterpret_cast<float4*>(z);
    float mx = -1e30f;
    for (int i = tid; i < MSET / 4; i += 256) {
        float4 v = s4[i];
        z4[i] = v;
        mx = fmaxf(mx, fmaxf(fmaxf(v.x, v.y), fmaxf(v.z, v.w)));
    }
    mx = block_max(mx, bufA);

    float tau = mx - 1.0f;
    for (int it = 0; it < 64; ++it) {
        float s = 0.f, c = 0.f;
        for (int i = tid; i < MSET; i += 256) {
            float v = z[i];
            if (v > tau) { s += v; c += 1.f; }
        }
        s = block_sum(s, bufA);
        c = block_sum(c, bufB);
        float tn = (s - 1.0f) / c;
        if (!(tn > tau)) break;
        tau = tn;
    }

    if (tid == 0) sh_pos = 0;
    __syncthreads();
    int* il = g_idx + row * (size_t)CAP;
    float* wl = g_w + row * (size_t)CAP;
    for (int i = tid; i < MSET; i += 256) {
        float v = z[i] - tau;
        if (v > 0.f) {
            int p = atomicAdd(&sh_pos, 1);
            if (p < CAP) { il[p] = i; wl[p] = v; }
        }
    }
    __syncthreads();
    int total = sh_pos;
    if (total > CAP) {
        for (int i = tid; i < MSET; i += 256) srow[i] = fmaxf(z[i] - tau, 0.f);
        if (tid == 0) g_cnt[row] = -1;
    } else {
        if (tid == 0) g_cnt[row] = total;
    }
}

// ---------------- 4) memory_vector = CW @ memory_set (sparse gather) ----------------
__global__ __launch_bounds__(256) void sparse_mv(const float* __restrict__ mem) {
    size_t row = blockIdx.x;
    int tid = threadIdx.x;
    int cnt = g_cnt[row];
    const float4* Y4 = reinterpret_cast<const float4*>(mem);
    float4 acc = make_float4(0.f, 0.f, 0.f, 0.f);

    if (cnt >= 0) {
        const int* il = g_idx + row * (size_t)CAP;
        const float* wl = g_w + row * (size_t)CAP;
        int t = 0;
        for (; t + 4 <= cnt; t += 4) {
#pragma unroll
            for (int u = 0; u < 4; u++) {
                int j = il[t + u];
                float w = wl[t + u];
                float4 y = Y4[(size_t)j * (DIM / 4) + tid];
                acc.x = fmaf(w, y.x, acc.x);
                acc.y = fmaf(w, y.y, acc.y);
                acc.z = fmaf(w, y.z, acc.z);
                acc.w = fmaf(w, y.w, acc.w);
            }
        }
        for (; t < cnt; t++) {
            int j = il[t];
            float w = wl[t];
            float4 y = Y4[(size_t)j * (DIM / 4) + tid];
            acc.x = fmaf(w, y.x, acc.x);
            acc.y = fmaf(w, y.y, acc.y);
            acc.z = fmaf(w, y.z, acc.z);
            acc.w = fmaf(w, y.w, acc.w);
        }
    } else {
        const float* srow = g_S + row * (size_t)MSET;
        for (int j = 0; j < MSET; j++) {
            float w = srow[j];
            if (w > 0.f) {
                float4 y = Y4[(size_t)j * (DIM / 4) + tid];
                acc.x = fmaf(w, y.x, acc.x);
                acc.y = fmaf(w, y.y, acc.y);
                acc.z = fmaf(w, y.z, acc.z);
                acc.w = fmaf(w, y.w, acc.w);
            }
        }
    }
    reinterpret_cast<float4*>(g_MV)[row * (DIM / 4) + tid] = acc;
}

// ---------------- 5) concat [enc | mv] -> FIh (half) ----------------
__global__ __launch_bounds__(256) void concat_kernel(const float* __restrict__ enc) {
    size_t i = (size_t)blockIdx.x * 256 + threadIdx.x;   // float4 index over [BATCH, 512]
    size_t row = i >> 9;
    int c4 = (int)(i & 511);
    float4 v;
    if (c4 < 256) v = reinterpret_cast<const float4*>(enc)[row * 256 + c4];
    else          v = reinterpret_cast<const float4*>(g_MV)[row * 256 + (c4 - 256)];
    __half2 h0 = __floats2half2_rn(v.x, v.y);
    __half2 h1 = __floats2half2_rn(v.z, v.w);
    uint2 u = make_uint2(*reinterpret_cast<unsigned*>(&h0), *reinterpret_cast<unsigned*>(&h1));
    reinterpret_cast<uint2*>(g_FIh)[i] = u;
}

// ---------------- launch ----------------
extern "C" void kernel_launch(void* const* d_in, const int* in_sizes, int n_in,
                              void* d_out, int out_size) {
    const float* enc = (const float*)d_in[0];
    const float* mem = (const float*)d_in[1];
    const float* W1 = (const float*)d_in[3];
    const float* b1 = (const float*)d_in[4];
    const float* W2 = (const float*)d_in[5];
    const float* b2 = (const float*)d_in[6];
    float* out = (float*)d_out;

    cudaFuncSetAttribute(gemm_fp16<0, false, false, false>,
                         cudaFuncAttributeMaxDynamicSharedMemorySize, GEMM_SMEM_BYTES);
    cudaFuncSetAttribute(gemm_fp16<1, true, true, false>,
                         cudaFuncAttributeMaxDynamicSharedMemorySize, GEMM_SMEM_BYTES);
    cudaFuncSetAttribute(gemm_fp16<2, true, false, true>,
                         cudaFuncAttributeMaxDynamicSharedMemorySize, GEMM_SMEM_BYTES);

    normalize_rows<0><<<BATCH, 256>>>(enc);
    normalize_rows<1><<<MSET, 256>>>(mem);
    conv_weights<0><<<(HID * 2 * DIM / 4 + 255) / 256, 256>>>(W1, HID * 2 * DIM / 4, HID * 2 * DIM / 4);
    conv_weights<1><<<(OUTP * HID / 4 + 255) / 256, 256>>>(W2, OUTD * HID / 4, OUTP * HID / 4);

    {   // S = XN @ YN^T   [4096 x 8192], K=1024
        dim3 grid(MSET / 128, BATCH / 128);
        gemm_fp16<0, false, false, false><<<grid, 128, GEMM_SMEM_BYTES>>>(nullptr, nullptr, MSET, DIM);
    }

    sparsemax_kernel<<<BATCH, 256>>>();
    sparse_mv<<<BATCH, 256>>>(mem);
    concat_kernel<<<(BATCH * 512) / 256, 256>>>(enc);

    {   // H = relu(FI @ W1^T + b1)  [4096 x 4096], K=2048
        dim3 grid(HID / 128, BATCH / 128);
        gemm_fp16<1, true, true, false><<<grid, 128, GEMM_SMEM_BYTES>>>(b1, nullptr, HID, 2 * DIM);
    }
    {   // out = H @ W2^T + b2  [4096 x 1000], K=4096 (N padded to 1024)
        dim3 grid(OUTP / 128, BATCH / 128);
        gemm_fp16<2, true, false, true><<<grid, 128, GEMM_SMEM_BYTES>>>(b2, out, OUTD, HID);
    }
}